// round 4
// baseline (speedup 1.0000x reference)
#include <cuda_runtime.h>

// Problem constants
#define Bv   8
#define SQv  2048
#define SKv  2048
#define Dv   512
#define Hv   8
#define QPv  512
#define VPv  4096
#define DQv  64     // QP / H
#define DVv  512    // VP / H

// GEMM tiling
#define BM 128
#define BN 128
#define BKK 8
#define TM 8
#define TN 8
#define NTHREADS 256

// Scratch (static device allocations — allowed; runtime alloc is not)
__device__ float g_q[(size_t)Bv * SQv * QPv];            // 33.5 MB
__device__ float g_k[(size_t)Bv * SKv * QPv];            // 33.5 MB
__device__ float g_v[(size_t)Bv * SKv * VPv];            // 268 MB
__device__ float g_S[(size_t)Bv * Hv * SQv * SKv];       // 1.07 GB
__device__ float g_O[(size_t)Hv * Bv * SQv * DVv];       // 268 MB  layout [h][b][s][d]

// ---------------------------------------------------------------------------
// Core tile GEMM: C[BMxBN] += A[BMxK] * B[KxBN]   (A,B,C row-major w/ strides)
// 256 threads, each computes an 8x8 microtile. All dims assumed multiples of
// tile sizes (true for this problem: 16384/2048 x 512/2048/4096, K % 8 == 0).
// ---------------------------------------------------------------------------
__device__ __forceinline__ void gemm_tile_nn(
    const float* __restrict__ A, int lda,
    const float* __restrict__ Bm, int ldb,
    float* __restrict__ C, int ldc,
    const float* __restrict__ bias,
    int K)
{
    __shared__ float As[BKK][BM];
    __shared__ float Bs[BKK][BN];

    const int tid  = threadIdx.x;
    const int m0   = blockIdx.y * BM;
    const int n0   = blockIdx.x * BN;
    const int tr   = tid >> 4;          // 0..15
    const int tc   = tid & 15;          // 0..15
    const int arow = tid >> 1;          // 0..127
    const int acol = (tid & 1) * 4;     // 0 or 4
    const int brow = tid >> 5;          // 0..7
    const int bcol = (tid & 31) * 4;    // 0..124

    float acc[TM][TN];
    #pragma unroll
    for (int i = 0; i < TM; ++i)
        #pragma unroll
        for (int j = 0; j < TN; ++j) acc[i][j] = 0.f;

    for (int k0 = 0; k0 < K; k0 += BKK) {
        float4 av = *(const float4*)&A[(long long)(m0 + arow) * lda + k0 + acol];
        As[acol + 0][arow] = av.x;
        As[acol + 1][arow] = av.y;
        As[acol + 2][arow] = av.z;
        As[acol + 3][arow] = av.w;
        float4 bv = *(const float4*)&Bm[(long long)(k0 + brow) * ldb + n0 + bcol];
        *(float4*)&Bs[brow][bcol] = bv;
        __syncthreads();

        #pragma unroll
        for (int k = 0; k < BKK; ++k) {
            float a[TM], b[TN];
            *(float4*)&a[0] = *(const float4*)&As[k][tr * TM];
            *(float4*)&a[4] = *(const float4*)&As[k][tr * TM + 4];
            *(float4*)&b[0] = *(const float4*)&Bs[k][tc * TN];
            *(float4*)&b[4] = *(const float4*)&Bs[k][tc * TN + 4];
            #pragma unroll
            for (int i = 0; i < TM; ++i)
                #pragma unroll
                for (int j = 0; j < TN; ++j)
                    acc[i][j] = fmaf(a[i], b[j], acc[i][j]);
        }
        __syncthreads();
    }

    #pragma unroll
    for (int i = 0; i < TM; ++i) {
        long long m = m0 + tr * TM + i;
        #pragma unroll
        for (int j = 0; j < TN; j += 4) {
            int n = n0 + tc * TN + j;
            float4 o;
            o.x = acc[i][j + 0] + (bias ? bias[n + 0] : 0.f);
            o.y = acc[i][j + 1] + (bias ? bias[n + 1] : 0.f);
            o.z = acc[i][j + 2] + (bias ? bias[n + 2] : 0.f);
            o.w = acc[i][j + 3] + (bias ? bias[n + 3] : 0.f);
            *(float4*)&C[m * ldc + n] = o;
        }
    }
}

// NT variant: C = A * B^T, with B stored N x K row-major (stride ldb)
__device__ __forceinline__ void gemm_tile_nt(
    const float* __restrict__ A, int lda,
    const float* __restrict__ Bt, int ldb,
    float* __restrict__ C, int ldc,
    int K)
{
    __shared__ float As[BKK][BM];
    __shared__ float Bs[BKK][BN];

    const int tid  = threadIdx.x;
    const int m0   = blockIdx.y * BM;
    const int n0   = blockIdx.x * BN;
    const int tr   = tid >> 4;
    const int tc   = tid & 15;
    const int arow = tid >> 1;          // 0..127
    const int acol = (tid & 1) * 4;     // 0 or 4

    float acc[TM][TN];
    #pragma unroll
    for (int i = 0; i < TM; ++i)
        #pragma unroll
        for (int j = 0; j < TN; ++j) acc[i][j] = 0.f;

    for (int k0 = 0; k0 < K; k0 += BKK) {
        float4 av = *(const float4*)&A[(long long)(m0 + arow) * lda + k0 + acol];
        As[acol + 0][arow] = av.x;
        As[acol + 1][arow] = av.y;
        As[acol + 2][arow] = av.z;
        As[acol + 3][arow] = av.w;
        float4 bv = *(const float4*)&Bt[(long long)(n0 + arow) * ldb + k0 + acol];
        Bs[acol + 0][arow] = bv.x;
        Bs[acol + 1][arow] = bv.y;
        Bs[acol + 2][arow] = bv.z;
        Bs[acol + 3][arow] = bv.w;
        __syncthreads();

        #pragma unroll
        for (int k = 0; k < BKK; ++k) {
            float a[TM], b[TN];
            *(float4*)&a[0] = *(const float4*)&As[k][tr * TM];
            *(float4*)&a[4] = *(const float4*)&As[k][tr * TM + 4];
            *(float4*)&b[0] = *(const float4*)&Bs[k][tc * TN];
            *(float4*)&b[4] = *(const float4*)&Bs[k][tc * TN + 4];
            #pragma unroll
            for (int i = 0; i < TM; ++i)
                #pragma unroll
                for (int j = 0; j < TN; ++j)
                    acc[i][j] = fmaf(a[i], b[j], acc[i][j]);
        }
        __syncthreads();
    }

    #pragma unroll
    for (int i = 0; i < TM; ++i) {
        long long m = m0 + tr * TM + i;
        #pragma unroll
        for (int j = 0; j < TN; j += 4) {
            int n = n0 + tc * TN + j;
            *(float4*)&C[m * ldc + n] = *(float4*)&acc[i][j];
        }
    }
}

// ---------------------------------------------------------------------------
// Kernels
// ---------------------------------------------------------------------------

// q = q_in @ W_q  (16384 x 512 @ 512 x 512)
__global__ void k_proj_q(const float* __restrict__ X, const float* __restrict__ W) {
    gemm_tile_nn(X, Dv, W, QPv, g_q, QPv, nullptr, Dv);
}
// k = k_in @ W_k
__global__ void k_proj_k(const float* __restrict__ X, const float* __restrict__ W) {
    gemm_tile_nn(X, Dv, W, QPv, g_k, QPv, nullptr, Dv);
}
// v = v_in @ W_v  (16384 x 4096)
__global__ void k_proj_v(const float* __restrict__ X, const float* __restrict__ W) {
    gemm_tile_nn(X, Dv, W, VPv, g_v, VPv, nullptr, Dv);
}

// S[b,h] = Q_h @ K_h^T   (2048 x 2048, K = 64), grid.z = b*H + h
__global__ void k_qk() {
    int p = blockIdx.z;
    int b = p >> 3, h = p & 7;
    const float* Qh = g_q + (long long)b * SQv * QPv + h * DQv;
    const float* Kh = g_k + (long long)b * SKv * QPv + h * DQv;
    float* Sp = g_S + (long long)p * SQv * SKv;
    gemm_tile_nt(Qh, QPv, Kh, QPv, Sp, SKv, DQv);
}

// In-place masked softmax over rows of S. grid = (SQ, B*H), 256 threads.
__global__ void k_softmax() {
    const int p = blockIdx.y;
    const int b = p >> 3;
    const int i = blockIdx.x;
    float* row = g_S + ((long long)p * SQv + i) * SKv;
    const int tid = threadIdx.x;

    // mask pointer comes from a device-visible copy set up by kernel args;
    // we read it via the global pointer stored below.
    extern __shared__ float sred[];   // 256 floats
    const int* mrow = ((const int* const*)0 == 0) ? nullptr : nullptr; // placeholder (unused)
    (void)mrow;

    // mask is passed through constant kernel parameter instead:
    // (see k_softmax_m below)
    (void)row; (void)b; (void)tid; (void)sred;
}

// Real softmax kernel (takes mask pointer as parameter)
__global__ void k_softmax_m(const int* __restrict__ mask) {
    const int p = blockIdx.y;          // b*H + h
    const int b = p >> 3;
    const int i = blockIdx.x;
    float* __restrict__ row = g_S + ((long long)p * SQv + i) * SKv;
    const int* __restrict__ mrow = mask + ((long long)b * SQv + i) * SKv;
    const int tid = threadIdx.x;       // 256 threads, 8 elems each

    __shared__ float red[256];

    float v[8];
    float mx = -3.402823466e+38f;
    #pragma unroll
    for (int t = 0; t < 8; ++t) {
        int j = tid + t * 256;
        float x = row[j];
        if (mrow[j] == 0) x = -1e9f;
        x *= 0.125f;                   // / sqrt(512/8) = /8
        v[t] = x;
        mx = fmaxf(mx, x);
    }
    red[tid] = mx;
    __syncthreads();
    for (int s = 128; s > 0; s >>= 1) {
        if (tid < s) red[tid] = fmaxf(red[tid], red[tid + s]);
        __syncthreads();
    }
    mx = red[0];
    __syncthreads();

    float sum = 0.f;
    #pragma unroll
    for (int t = 0; t < 8; ++t) {
        v[t] = expf(v[t] - mx);
        sum += v[t];
    }
    red[tid] = sum;
    __syncthreads();
    for (int s = 128; s > 0; s >>= 1) {
        if (tid < s) red[tid] += red[tid + s];
        __syncthreads();
    }
    sum = red[0];

    float inv = 1.f / sum;
    #pragma unroll
    for (int t = 0; t < 8; ++t)
        row[tid + t * 256] = v[t] * inv;
}

// O[h,b] = S[b,h] @ V_h  (2048 x 512, K = 2048).  Note (h,b) pair order in O
// reproduces the reference's transpose(1,0,2,3)+reshape exactly.
__global__ void k_pv() {
    int p = blockIdx.z;
    int b = p >> 3, h = p & 7;
    const float* Sp = g_S + (long long)p * SQv * SKv;
    const float* Vh = g_v + (long long)b * SKv * VPv + h * DVv;
    float* Op = g_O + ((long long)(h * Bv + b)) * SQv * DVv;
    gemm_tile_nn(Sp, SKv, Vh, VPv, Op, DVv, nullptr, SKv);
}

// out = O @ W_o + b_o  (16384 x 4096 @ 4096 x 512)
__global__ void k_out(const float* __restrict__ Wo, const float* __restrict__ bo,
                      float* __restrict__ out) {
    gemm_tile_nn(g_O, VPv, Wo, Dv, out, Dv, bo, VPv);
}

// ---------------------------------------------------------------------------
// Launch
// ---------------------------------------------------------------------------
extern "C" void kernel_launch(void* const* d_in, const int* in_sizes, int n_in,
                              void* d_out, int out_size) {
    const float* q_in = (const float*)d_in[0];
    const float* k_in = (const float*)d_in[1];
    const float* v_in = (const float*)d_in[2];
    const float* W_q  = (const float*)d_in[3];
    const float* W_k  = (const float*)d_in[4];
    const float* W_v  = (const float*)d_in[5];
    const float* W_o  = (const float*)d_in[6];
    const float* b_o  = (const float*)d_in[7];
    const int*   mask = (const int*)d_in[8];
    float* out = (float*)d_out;

    const int MROWS = Bv * SQv;  // 16384

    dim3 blk(NTHREADS);

    // Projections
    k_proj_q<<<dim3(QPv / BN, MROWS / BM), blk>>>(q_in, W_q);
    k_proj_k<<<dim3(QPv / BN, MROWS / BM), blk>>>(k_in, W_k);
    k_proj_v<<<dim3(VPv / BN, MROWS / BM), blk>>>(v_in, W_v);

    // Attention scores
    k_qk<<<dim3(SKv / BN, SQv / BM, Bv * Hv), blk>>>();

    // Masked + scaled softmax (in place on S)
    k_softmax_m<<<dim3(SQv, Bv * Hv), blk>>>(mask);

    // PV
    k_pv<<<dim3(DVv / BN, SQv / BM, Bv * Hv), blk>>>();

    // Output projection + bias
    k_out<<<dim3(Dv / BN, MROWS / BM), blk>>>(W_o, b_o, out);
}

// round 6
// speedup vs baseline: 3.4127x; 3.4127x over previous
#include <cuda_runtime.h>
#include <cstdint>

// Problem constants
#define Bv   8
#define SQv  2048
#define SKv  2048
#define Dv   512
#define Hv   8
#define QPv  512
#define VPv  4096

// ---------------------------------------------------------------------------
// Scratch
// ---------------------------------------------------------------------------
__device__ float g_xq [(size_t)Bv * SQv * Dv];           // rounded q_in
__device__ float g_xk [(size_t)Bv * SKv * Dv];           // rounded k_in
__device__ float g_xv [(size_t)Bv * SKv * Dv];           // rounded v_in
__device__ float g_q  [(size_t)Bv * SQv * QPv];
__device__ float g_k  [(size_t)Bv * SKv * QPv];
__device__ float g_vT [(size_t)Bv * VPv * SKv];          // [b][vp][sk]
__device__ float g_S  [(size_t)Bv * Hv * SQv * SKv];     // 1.07 GB
__device__ float g_O  [(size_t)Hv * Bv * SQv * (VPv/Hv)];// [h][b][sq][dv]
__device__ float g_wqT[(size_t)QPv * Dv];
__device__ float g_wkT[(size_t)QPv * Dv];
__device__ float g_wvT[(size_t)VPv * Dv];
__device__ float g_woT[(size_t)Dv * VPv];

// ---------------------------------------------------------------------------
// Helpers
// ---------------------------------------------------------------------------
__device__ __forceinline__ float rnd_tf32(float x) {
    uint32_t r; asm("cvt.rna.tf32.f32 %0, %1;" : "=r"(r) : "f"(x));
    return __uint_as_float(r);
}
__device__ __forceinline__ uint32_t smem_u32(const void* p) {
    uint32_t a;
    asm("{ .reg .u64 t; cvta.to.shared.u64 t, %1; cvt.u32.u64 %0, t; }"
        : "=r"(a) : "l"(p));
    return a;
}
__device__ __forceinline__ void cp16(uint32_t dst, const void* src) {
    asm volatile("cp.async.cg.shared.global [%0], [%1], 16;"
                 :: "r"(dst), "l"(src) : "memory");
}
__device__ __forceinline__ void cp_commit() {
    asm volatile("cp.async.commit_group;" ::: "memory");
}
template<int N> __device__ __forceinline__ void cp_wait() {
    asm volatile("cp.async.wait_group %0;" :: "n"(N) : "memory");
}
__device__ __forceinline__ void mma_tf32(float* c, const uint32_t* a, const uint32_t* b) {
    asm volatile(
        "mma.sync.aligned.m16n8k8.row.col.f32.tf32.tf32.f32 "
        "{%0,%1,%2,%3},{%4,%5,%6,%7},{%8,%9},{%0,%1,%2,%3};"
        : "+f"(c[0]), "+f"(c[1]), "+f"(c[2]), "+f"(c[3])
        : "r"(a[0]), "r"(a[1]), "r"(a[2]), "r"(a[3]),
          "r"(b[0]), "r"(b[1]));
}

// ---------------------------------------------------------------------------
// HMMA tf32 GEMM:  C[128 x 128] tile of  C = A * B^T  (+bias)
// A: M x K (lda), B: N x K (ldb), both K-major, tf32-prerounded. K % 32 == 0.
// MODE 0: plain       MODE 1: qk per-pair       MODE 2: pv per-pair
// MODE 3: plain compute, TRANSPOSED epilogue into g_vT [b][vp][sk]
// ROUND: cvt.rna.tf32 applied to outputs (when they feed a later MMA)
// ---------------------------------------------------------------------------
#define BKt   32
#define LDS_A 36          // 32 + 4 pad floats
#define TILEF (128 * LDS_A)   // floats per buffer

template<int MODE, int ROUND>
__global__ void __launch_bounds__(256, 2) gemm_hmma(
    const float* __restrict__ Ag, const float* __restrict__ Bg,
    float* __restrict__ Cg, const float* __restrict__ bias,
    int K, int lda, int ldb, int ldc)
{
    extern __shared__ float smf[];
    const int tid  = threadIdx.x;
    const int warp = tid >> 5;
    const int lane = tid & 31;
    const int qr   = lane >> 2;      // 0..7
    const int qc   = lane & 3;       // 0..3
    const int wm   = warp >> 2;      // 0..1  (warp m-tile 64)
    const int wn   = warp & 3;       // 0..3  (warp n-tile 32)
    const uint32_t sbase = smem_u32(smf);

    const int m0 = blockIdx.y * 128, n0 = blockIdx.x * 128;
    const float *A, *B; float *C;
    if (MODE == 1) {
        int p = blockIdx.z, b = p >> 3, h = p & 7;
        A = Ag + (size_t)b * SQv * QPv + h * 64;
        B = Bg + (size_t)b * SKv * QPv + h * 64;
        C = Cg + (size_t)p * SQv * SKv;
    } else if (MODE == 2) {
        int p = blockIdx.z, b = p >> 3, h = p & 7;
        A = Ag + (size_t)p * SQv * SKv;
        B = Bg + ((size_t)b * VPv + h * 512) * SKv;
        C = Cg + (size_t)(h * Bv + b) * SQv * 512;
    } else { A = Ag; B = Bg; C = Cg; }

    const float* Abase = A + (size_t)m0 * lda;
    const float* Bbase = B + (size_t)n0 * ldb;

    // smem: As[2][128][36], Bs[2][128][36]
    auto issue_tile = [&](const float* G, int ld, int k0, int foff) {
        #pragma unroll
        for (int i = 0; i < 4; ++i) {
            int idx = tid + i * 256;           // 0..1023
            int r = idx >> 3, s = idx & 7;
            cp16(sbase + (uint32_t)(foff + r * LDS_A + s * 4) * 4,
                 G + (size_t)r * ld + k0 + s * 4);
        }
    };

    float acc[4][4][4];
    #pragma unroll
    for (int mi = 0; mi < 4; ++mi)
        #pragma unroll
        for (int ni = 0; ni < 4; ++ni)
            #pragma unroll
            for (int j = 0; j < 4; ++j) acc[mi][ni][j] = 0.f;

    const int NC = K / BKt;
    issue_tile(Abase, lda, 0, 0);
    issue_tile(Bbase, ldb, 0, 2 * TILEF);
    cp_commit();

    for (int c = 0; c < NC; ++c) {
        const int bi = c & 1;
        if (c + 1 < NC) {
            issue_tile(Abase, lda, (c + 1) * BKt, (1 - bi) * TILEF);
            issue_tile(Bbase, ldb, (c + 1) * BKt, 2 * TILEF + (1 - bi) * TILEF);
            cp_commit();
            cp_wait<1>();
        } else {
            cp_wait<0>();
        }
        __syncthreads();

        const float* As = smf + bi * TILEF;
        const float* Bs = smf + 2 * TILEF + bi * TILEF;
        #pragma unroll
        for (int k8 = 0; k8 < 4; ++k8) {
            const int kb = k8 * 8;
            uint32_t a[4][4], b[4][2];
            #pragma unroll
            for (int mi = 0; mi < 4; ++mi) {
                const float* ap = As + (wm * 64 + mi * 16 + qr) * LDS_A + kb + qc;
                a[mi][0] = __float_as_uint(ap[0]);
                a[mi][1] = __float_as_uint(ap[8 * LDS_A]);
                a[mi][2] = __float_as_uint(ap[4]);
                a[mi][3] = __float_as_uint(ap[8 * LDS_A + 4]);
            }
            #pragma unroll
            for (int ni = 0; ni < 4; ++ni) {
                const float* bp = Bs + (wn * 32 + ni * 8 + qr) * LDS_A + kb + qc;
                b[ni][0] = __float_as_uint(bp[0]);
                b[ni][1] = __float_as_uint(bp[4]);
            }
            #pragma unroll
            for (int mi = 0; mi < 4; ++mi)
                #pragma unroll
                for (int ni = 0; ni < 4; ++ni)
                    mma_tf32(acc[mi][ni], a[mi], b[ni]);
        }
        __syncthreads();
    }

    // ---- epilogue -------------------------------------------------------
    if (MODE == 3) {
        // stage transposed: stg[n][m], stride 132 (conflict-free both sides)
        float* stg = smf;
        #pragma unroll
        for (int mi = 0; mi < 4; ++mi)
            #pragma unroll
            for (int ni = 0; ni < 4; ++ni) {
                int m = wm * 64 + mi * 16 + qr;
                int n = wn * 32 + ni * 8 + 2 * qc;
                stg[(size_t)n * 132 + m]           = acc[mi][ni][0];
                stg[(size_t)(n + 1) * 132 + m]     = acc[mi][ni][1];
                stg[(size_t)n * 132 + m + 8]       = acc[mi][ni][2];
                stg[(size_t)(n + 1) * 132 + m + 8] = acc[mi][ni][3];
            }
        __syncthreads();
        const int b = m0 >> 11, sk0 = m0 & 2047;
        float* dst = Cg + (size_t)b * VPv * SKv + sk0;
        for (int idx = tid; idx < 128 * 32; idx += 256) {
            int n = idx >> 5, mc = idx & 31;
            float4 t = *(float4*)&stg[(size_t)n * 132 + mc * 4];
            t.x = rnd_tf32(t.x); t.y = rnd_tf32(t.y);
            t.z = rnd_tf32(t.z); t.w = rnd_tf32(t.w);
            *(float4*)&dst[(size_t)(n0 + n) * SKv + mc * 4] = t;
        }
    } else {
        #pragma unroll
        for (int mi = 0; mi < 4; ++mi) {
            const int r0 = m0 + wm * 64 + mi * 16 + qr;
            #pragma unroll
            for (int ni = 0; ni < 4; ++ni) {
                const int nb = n0 + wn * 32 + ni * 8 + 2 * qc;
                float2 v0, v1;
                v0.x = acc[mi][ni][0]; v0.y = acc[mi][ni][1];
                v1.x = acc[mi][ni][2]; v1.y = acc[mi][ni][3];
                if (bias) {
                    v0.x += bias[nb]; v0.y += bias[nb + 1];
                    v1.x += bias[nb]; v1.y += bias[nb + 1];
                }
                if (ROUND) {
                    v0.x = rnd_tf32(v0.x); v0.y = rnd_tf32(v0.y);
                    v1.x = rnd_tf32(v1.x); v1.y = rnd_tf32(v1.y);
                }
                *(float2*)&C[(size_t)r0 * ldc + nb]       = v0;
                *(float2*)&C[(size_t)(r0 + 8) * ldc + nb] = v1;
            }
        }
    }
}

// ---------------------------------------------------------------------------
// Elementwise tf32 pre-round (inputs)
// ---------------------------------------------------------------------------
__global__ void k_round(const float* __restrict__ in, float* __restrict__ out,
                        size_t n4) {
    size_t i = (size_t)blockIdx.x * blockDim.x + threadIdx.x;
    if (i < n4) {
        float4 v = ((const float4*)in)[i];
        v.x = rnd_tf32(v.x); v.y = rnd_tf32(v.y);
        v.z = rnd_tf32(v.z); v.w = rnd_tf32(v.w);
        ((float4*)out)[i] = v;
    }
}

// ---------------------------------------------------------------------------
// Weight transpose + tf32 round: out[c][r] = tf32(in[r][c])
// ---------------------------------------------------------------------------
__global__ void k_transpose(const float* __restrict__ in, float* __restrict__ out,
                            int rows, int cols) {
    __shared__ float t[32][33];
    const int c0 = blockIdx.x * 32, r0 = blockIdx.y * 32;
    const int x = threadIdx.x, y = threadIdx.y;      // 32 x 8
    #pragma unroll
    for (int i = 0; i < 32; i += 8)
        t[y + i][x] = in[(size_t)(r0 + y + i) * cols + c0 + x];
    __syncthreads();
    #pragma unroll
    for (int i = 0; i < 32; i += 8)
        out[(size_t)(c0 + y + i) * rows + r0 + x] = rnd_tf32(t[x][y + i]);
}

// ---------------------------------------------------------------------------
// Masked + scaled softmax (in place on g_S), output tf32-rounded
// ---------------------------------------------------------------------------
__global__ void k_softmax_m(const int* __restrict__ mask) {
    const int p = blockIdx.y;          // b*H + h
    const int b = p >> 3;
    const int i = blockIdx.x;
    float* __restrict__ row = g_S + ((size_t)p * SQv + i) * SKv;
    const int* __restrict__ mrow = mask + ((size_t)b * SQv + i) * SKv;
    const int tid = threadIdx.x;

    __shared__ float red[256];

    float v[8];
    float mx = -3.402823466e+38f;
    #pragma unroll
    for (int t = 0; t < 8; ++t) {
        int j = tid + t * 256;
        float x = row[j];
        if (mrow[j] == 0) x = -1e9f;
        x *= 0.125f;                   // / sqrt(512/8)
        v[t] = x;
        mx = fmaxf(mx, x);
    }
    red[tid] = mx;
    __syncthreads();
    for (int s = 128; s > 0; s >>= 1) {
        if (tid < s) red[tid] = fmaxf(red[tid], red[tid + s]);
        __syncthreads();
    }
    mx = red[0];
    __syncthreads();

    float sum = 0.f;
    #pragma unroll
    for (int t = 0; t < 8; ++t) { v[t] = expf(v[t] - mx); sum += v[t]; }
    red[tid] = sum;
    __syncthreads();
    for (int s = 128; s > 0; s >>= 1) {
        if (tid < s) red[tid] += red[tid + s];
        __syncthreads();
    }
    sum = red[0];

    const float inv = 1.f / sum;
    #pragma unroll
    for (int t = 0; t < 8; ++t)
        row[tid + t * 256] = rnd_tf32(v[t] * inv);
}

// ---------------------------------------------------------------------------
// Launch
// ---------------------------------------------------------------------------
extern "C" void kernel_launch(void* const* d_in, const int* in_sizes, int n_in,
                              void* d_out, int out_size) {
    const float* q_in = (const float*)d_in[0];
    const float* k_in = (const float*)d_in[1];
    const float* v_in = (const float*)d_in[2];
    const float* W_q  = (const float*)d_in[3];
    const float* W_k  = (const float*)d_in[4];
    const float* W_v  = (const float*)d_in[5];
    const float* W_o  = (const float*)d_in[6];
    const float* b_o  = (const float*)d_in[7];
    const int*   mask = (const int*)d_in[8];
    float* out = (float*)d_out;

    float *pxq, *pxk, *pxv, *pq, *pk, *pvT, *pS, *pO, *pwqT, *pwkT, *pwvT, *pwoT;
    cudaGetSymbolAddress((void**)&pxq,  g_xq);
    cudaGetSymbolAddress((void**)&pxk,  g_xk);
    cudaGetSymbolAddress((void**)&pxv,  g_xv);
    cudaGetSymbolAddress((void**)&pq,   g_q);
    cudaGetSymbolAddress((void**)&pk,   g_k);
    cudaGetSymbolAddress((void**)&pvT,  g_vT);
    cudaGetSymbolAddress((void**)&pS,   g_S);
    cudaGetSymbolAddress((void**)&pO,   g_O);
    cudaGetSymbolAddress((void**)&pwqT, g_wqT);
    cudaGetSymbolAddress((void**)&pwkT, g_wkT);
    cudaGetSymbolAddress((void**)&pwvT, g_wvT);
    cudaGetSymbolAddress((void**)&pwoT, g_woT);

    const int SMEM = 4 * TILEF * 4;   // 73728 bytes
    cudaFuncSetAttribute(gemm_hmma<0, 1>, cudaFuncAttributeMaxDynamicSharedMemorySize, SMEM);
    cudaFuncSetAttribute(gemm_hmma<0, 0>, cudaFuncAttributeMaxDynamicSharedMemorySize, SMEM);
    cudaFuncSetAttribute(gemm_hmma<1, 0>, cudaFuncAttributeMaxDynamicSharedMemorySize, SMEM);
    cudaFuncSetAttribute(gemm_hmma<2, 1>, cudaFuncAttributeMaxDynamicSharedMemorySize, SMEM);
    cudaFuncSetAttribute(gemm_hmma<3, 1>, cudaFuncAttributeMaxDynamicSharedMemorySize, SMEM);

    // Pre-round inputs to tf32 values
    const size_t nx4 = (size_t)Bv * SQv * Dv / 4;      // 2,097,152 float4
    k_round<<<(unsigned)((nx4 + 255) / 256), 256>>>(q_in, pxq, nx4);
    k_round<<<(unsigned)((nx4 + 255) / 256), 256>>>(k_in, pxk, nx4);
    k_round<<<(unsigned)((nx4 + 255) / 256), 256>>>(v_in, pxv, nx4);

    dim3 tb(32, 8);
    // Weight transposes + rounding (B operands must be [N][K] K-major)
    k_transpose<<<dim3(16, 16),  tb>>>(W_q, pwqT, Dv, QPv);
    k_transpose<<<dim3(16, 16),  tb>>>(W_k, pwkT, Dv, QPv);
    k_transpose<<<dim3(128, 16), tb>>>(W_v, pwvT, Dv, VPv);
    k_transpose<<<dim3(16, 128), tb>>>(W_o, pwoT, VPv, Dv);

    // q = q_in @ W_q ; k = k_in @ W_k      (16384 x 512, K=512) -> rounded
    gemm_hmma<0, 1><<<dim3(4, 128), 256, SMEM>>>(pxq, pwqT, pq, nullptr, 512, 512, 512, 512);
    gemm_hmma<0, 1><<<dim3(4, 128), 256, SMEM>>>(pxk, pwkT, pk, nullptr, 512, 512, 512, 512);

    // v = v_in @ W_v, written TRANSPOSED + rounded into g_vT [b][vp][sk]
    gemm_hmma<3, 1><<<dim3(32, 128), 256, SMEM>>>(pxv, pwvT, pvT, nullptr, 512, 512, 512, 0);

    // S[b,h] = Q_h @ K_h^T  (2048 x 2048, K=64), fp32 out (softmax rounds)
    gemm_hmma<1, 0><<<dim3(16, 16, 64), 256, SMEM>>>(pq, pk, pS, nullptr, 64, 512, 512, 2048);

    // masked + scaled softmax (rounds output to tf32)
    k_softmax_m<<<dim3(SQv, Bv * Hv), 256>>>(mask);

    // O[h,b] = S[b,h] @ V_h  (2048 x 512, K=2048) -> rounded; (h,b) order
    // reproduces the reference's transpose(1,0,2,3)+reshape.
    gemm_hmma<2, 1><<<dim3(4, 16, 64), 256, SMEM>>>(pS, pvT, pO, nullptr, 2048, 2048, 2048, 512);

    // out = O @ W_o + b_o   (16384 x 512, K=4096), fp32 out
    gemm_hmma<0, 0><<<dim3(4, 128), 256, SMEM>>>(pO, pwoT, out, b_o, 4096, 4096, 4096, 512);
}